// round 9
// baseline (speedup 1.0000x reference)
#include <cuda_runtime.h>
#include <cstdint>

namespace {
constexpr int N_NODES  = 100000;
constexpr int HID      = 64;
constexpr int N_LAYERS = 4;
constexpr int N_EDGES  = 800000;
constexpr float EPS    = 1e-5f;
constexpr int CAP      = 64;   // bucket capacity (Poisson(8); max deg ~< 40)
constexpr int SA_STR   = 68;   // padded smem row stride in floats (17 float4s)

// dynamic smem layout (float indices)
constexpr int OF_A   = 0;                    // 128 x 68 fp32 (A rows, fragment-order cols)
constexpr int OF_WHI = 128 * SA_STR;         // 64 x 68 tf32 bits (fragment-order cols)
constexpr int OF_WLO = OF_WHI + 64 * SA_STR;
constexpr int OF_CN  = OF_WLO + 64 * SA_STR; // 64 floats
constexpr int OF_HN  = OF_CN + 64;           // 64 floats
constexpr int SMEM_FLOATS = OF_HN + 64;
constexpr int SMEM_BYTES  = SMEM_FLOATS * 4; // 70144 B
}

// Scratch (no cudaMalloc allowed)
__device__ float g_m  [(size_t)N_NODES * HID];
__device__ float g_agg[(size_t)N_NODES * HID];
__device__ float g_h  [(size_t)N_NODES * HID];
__device__ int   g_deg[N_NODES];
__device__ int   g_bkt[(size_t)N_NODES * CAP];

// ---------------- helpers ----------------
__device__ __forceinline__ uint32_t tf32_of(float a) {
    uint32_t r; asm("cvt.rna.tf32.f32 %0, %1;" : "=r"(r) : "f"(a)); return r;
}
__device__ __forceinline__ void mma_tf32(float* c, const uint32_t* a,
                                         uint32_t b0, uint32_t b1) {
    asm volatile(
        "mma.sync.aligned.m16n8k8.row.col.f32.tf32.tf32.f32 "
        "{%0,%1,%2,%3},{%4,%5,%6,%7},{%8,%9},{%0,%1,%2,%3};"
        : "+f"(c[0]), "+f"(c[1]), "+f"(c[2]), "+f"(c[3])
        : "r"(a[0]), "r"(a[1]), "r"(a[2]), "r"(a[3]), "r"(b0), "r"(b1));
}

// fragment-order column permutation: original k -> col' = 8*(k&7) + (k>>3)
// (thread q's 8 k-step values for qoff land contiguous at [8*qoff .. 8*qoff+7])

// cooperatively split W (64x64 row-major, W[n][k]) into tf32 hi/lo smem tiles,
// permuted columns
__device__ __forceinline__ void load_W_split(float* sm, const float* __restrict__ W, int tid) {
    uint32_t* whi = (uint32_t*)(sm + OF_WHI);
    uint32_t* wlo = (uint32_t*)(sm + OF_WLO);
    for (int i = tid; i < HID * HID; i += 128) {
        int n = i >> 6, k = i & 63;
        int kp = ((k & 7) << 3) | (k >> 3);
        float w = __ldg(W + i);
        uint32_t hb = tf32_of(w);
        whi[n * SA_STR + kp] = hb;
        wlo[n * SA_STR + kp] = tf32_of(w - __uint_as_float(hb));
    }
}

// store one A row (v[64], natural order) into fragment-order smem row
__device__ __forceinline__ void store_A_row(float* sm, int row, const float* v) {
    float4* dst = (float4*)(sm + OF_A + row * SA_STR);
#pragma unroll
    for (int t = 0; t < 16; t++) {
        int qoff = t >> 1, k0 = ((t & 1) << 5) + qoff;  // 8*ks0 + qoff, ks0 = (t&1)*4
        dst[t] = make_float4(v[k0], v[k0 + 8], v[k0 + 16], v[k0 + 24]);
    }
}

#define UNPACK8F(dst, a, b) \
    { dst[0]=a.x; dst[1]=a.y; dst[2]=a.z; dst[3]=a.w; \
      dst[4]=b.x; dst[5]=b.y; dst[6]=b.z; dst[7]=b.w; }
#define UNPACK8U(dst, a, b) \
    { dst[0]=a.x; dst[1]=a.y; dst[2]=a.z; dst[3]=a.w; \
      dst[4]=b.x; dst[5]=b.y; dst[6]=b.z; dst[7]=b.w; }

// MMA mainloop for one m-tile (16 rows starting at rbase). acc[nt][4].
__device__ __forceinline__ void mma_mtile(const float* sm, int rbase, int g, int q,
                                          float acc[8][4]) {
    // ---- A fragments: rows g, g+8; qoffs q, q+4; contiguous float4 pairs ----
    const float4* Ag  = (const float4*)(sm + OF_A + (rbase + g) * SA_STR);
    const float4* Ag8 = (const float4*)(sm + OF_A + (rbase + g + 8) * SA_STR);
    float4 x0a = Ag [2 * q],     x0b = Ag [2 * q + 1];   // c0: row g,   qoff q
    float4 x1a = Ag8[2 * q],     x1b = Ag8[2 * q + 1];   // c1: row g+8, qoff q
    float4 x2a = Ag [2 * q + 8], x2b = Ag [2 * q + 9];   // c2: row g,   qoff q+4
    float4 x3a = Ag8[2 * q + 8], x3b = Ag8[2 * q + 9];   // c3: row g+8, qoff q+4
    float f0[8], f1[8], f2[8], f3[8];
    UNPACK8F(f0, x0a, x0b); UNPACK8F(f1, x1a, x1b);
    UNPACK8F(f2, x2a, x2b); UNPACK8F(f3, x3a, x3b);

    uint32_t ahi[8][4], alo[8][4];
#pragma unroll
    for (int ks = 0; ks < 8; ks++) {
        ahi[ks][0] = tf32_of(f0[ks]); alo[ks][0] = tf32_of(f0[ks] - __uint_as_float(ahi[ks][0]));
        ahi[ks][1] = tf32_of(f1[ks]); alo[ks][1] = tf32_of(f1[ks] - __uint_as_float(ahi[ks][1]));
        ahi[ks][2] = tf32_of(f2[ks]); alo[ks][2] = tf32_of(f2[ks] - __uint_as_float(ahi[ks][2]));
        ahi[ks][3] = tf32_of(f3[ks]); alo[ks][3] = tf32_of(f3[ks] - __uint_as_float(ahi[ks][3]));
    }

#pragma unroll
    for (int nt = 0; nt < 8; nt++) {
#pragma unroll
        for (int i = 0; i < 4; i++) acc[nt][i] = 0.f;
        const uint4* Bh = (const uint4*)((const uint32_t*)(sm + OF_WHI) + (8 * nt + g) * SA_STR);
        const uint4* Bl = (const uint4*)((const uint32_t*)(sm + OF_WLO) + (8 * nt + g) * SA_STR);
        uint4 h0a = Bh[2 * q],     h0b = Bh[2 * q + 1];
        uint4 h1a = Bh[2 * q + 8], h1b = Bh[2 * q + 9];
        uint4 l0a = Bl[2 * q],     l0b = Bl[2 * q + 1];
        uint4 l1a = Bl[2 * q + 8], l1b = Bl[2 * q + 9];
        uint32_t b0h[8], b1h[8], b0l[8], b1l[8];
        UNPACK8U(b0h, h0a, h0b); UNPACK8U(b1h, h1a, h1b);
        UNPACK8U(b0l, l0a, l0b); UNPACK8U(b1l, l1a, l1b);
#pragma unroll
        for (int ks = 0; ks < 8; ks++) {
            mma_tf32(acc[nt], ahi[ks], b0h[ks], b1h[ks]);   // hi*hi
            mma_tf32(acc[nt], ahi[ks], b0l[ks], b1l[ks]);   // hi*lo
            mma_tf32(acc[nt], alo[ks], b0h[ks], b1h[ks]);   // lo*hi
        }
    }
}

// =====================================================================
// Bucket build (once per launch). g_deg memset to 0 first.
// =====================================================================
__global__ void k_build(const int* __restrict__ row, const int* __restrict__ col) {
    int e = blockIdx.x * 256 + threadIdx.x;
    if (e >= N_EDGES) return;
    int r = __ldg(row + e);
    int p = atomicAdd(&g_deg[r], 1);
    if (p < CAP) g_bkt[(size_t)r * CAP + p] = __ldg(col + e);
}

// =====================================================================
// K1: m = relu(h @ Wc^T)  via mma.sync tf32 (3xTF32)
// =====================================================================
__global__ void __launch_bounds__(128) k_conv(
    const float* __restrict__ h, const float* __restrict__ W,
    float* __restrict__ m)
{
    extern __shared__ float sm[];
    int tid = threadIdx.x;

    load_W_split(sm, W, tid);

    int node = blockIdx.x * 128 + tid;
    bool valid = node < N_NODES;
    {
        const float4* hr = (const float4*)(h + (size_t)node * HID);
        float v[64];
#pragma unroll
        for (int c = 0; c < 16; c++) {
            float4 t = valid ? __ldg(hr + c) : make_float4(0.f, 0.f, 0.f, 0.f);
            v[4*c] = t.x; v[4*c+1] = t.y; v[4*c+2] = t.z; v[4*c+3] = t.w;
        }
        store_A_row(sm, tid, v);
    }
    __syncthreads();

    int wid = tid >> 5, lane = tid & 31, g = lane >> 2, q = lane & 3;
#pragma unroll
    for (int mt = 0; mt < 2; mt++) {
        int rbase = 32 * wid + 16 * mt;
        float acc[8][4];
        mma_mtile(sm, rbase, g, q, acc);

        int n0 = blockIdx.x * 128 + rbase + g;
        int n1 = n0 + 8;
        if (n0 < N_NODES) {
            float* mr = m + (size_t)n0 * HID + 2 * q;
#pragma unroll
            for (int nt = 0; nt < 8; nt++)
                *(float2*)(mr + 8 * nt) =
                    make_float2(fmaxf(acc[nt][0], 0.f), fmaxf(acc[nt][1], 0.f));
        }
        if (n1 < N_NODES) {
            float* mr = m + (size_t)n1 * HID + 2 * q;
#pragma unroll
            for (int nt = 0; nt < 8; nt++)
                *(float2*)(mr + 8 * nt) =
                    make_float2(fmaxf(acc[nt][2], 0.f), fmaxf(acc[nt][3], 0.f));
        }
    }
}

// =====================================================================
// K2: agg[r] = sum_{e: row[e]=r} m[col[e]]  — gather, 16 lanes/node
// =====================================================================
__global__ void __launch_bounds__(256) k_agg(
    const float4* __restrict__ m, float4* __restrict__ agg)
{
    int wid  = threadIdx.x >> 5;
    int lane = threadIdx.x & 31;
    int node = (blockIdx.x * 8 + wid) * 2 + (lane >> 4);
    if (node >= N_NODES) return;
    int l = lane & 15;

    int d = g_deg[node]; if (d > CAP) d = CAP;
    const int* bp = g_bkt + (size_t)node * CAP;

    float4 acc = make_float4(0.f, 0.f, 0.f, 0.f);
    int i = 0;
    for (; i + 2 <= d; i += 2) {
        int c0 = __ldg(bp + i);
        int c1 = __ldg(bp + i + 1);
        float4 v0 = __ldg(m + (size_t)c0 * 16 + l);
        float4 v1 = __ldg(m + (size_t)c1 * 16 + l);
        acc.x += v0.x + v1.x; acc.y += v0.y + v1.y;
        acc.z += v0.z + v1.z; acc.w += v0.w + v1.w;
    }
    if (i < d) {
        int c = __ldg(bp + i);
        float4 v = __ldg(m + (size_t)c * 16 + l);
        acc.x += v.x; acc.y += v.y; acc.z += v.z; acc.w += v.w;
    }
    agg[(size_t)node * 16 + l] = acc;
}

// =====================================================================
// K3: h' = rmsnorm(h+agg)*cnw;  y = relu(h' @ Wh^T)  (mma.sync 3xTF32);
//     out = rmsnorm(h'+y)*hnw
// =====================================================================
__global__ void __launch_bounds__(128) k_norm(
    const float* __restrict__ h, const float* __restrict__ agg,
    const float* __restrict__ W, const float* __restrict__ cnw,
    const float* __restrict__ hnw, float* __restrict__ out)
{
    extern __shared__ float sm[];
    int tid = threadIdx.x;

    if (tid < HID) {
        sm[OF_CN + tid] = __ldg(cnw + tid);
        sm[OF_HN + tid] = __ldg(hnw + tid);
    }
    load_W_split(sm, W, tid);
    __syncthreads();

    int node = blockIdx.x * 128 + tid;
    bool valid = node < N_NODES;
    {
        const float4* hr = (const float4*)(h   + (size_t)node * HID);
        const float4* ar = (const float4*)(agg + (size_t)node * HID);
        float v[64];
        float sq = 0.f;
#pragma unroll
        for (int c = 0; c < 16; c++) {
            float4 a = valid ? __ldg(hr + c) : make_float4(0.f, 0.f, 0.f, 0.f);
            float4 b = valid ? __ldg(ar + c) : make_float4(0.f, 0.f, 0.f, 0.f);
            float z0 = a.x + b.x, z1 = a.y + b.y, z2 = a.z + b.z, z3 = a.w + b.w;
            v[4*c] = z0; v[4*c+1] = z1; v[4*c+2] = z2; v[4*c+3] = z3;
            sq = fmaf(z0, z0, sq); sq = fmaf(z1, z1, sq);
            sq = fmaf(z2, z2, sq); sq = fmaf(z3, z3, sq);
        }
        float inv1 = rsqrtf(sq * (1.f / HID) + EPS);
#pragma unroll
        for (int k = 0; k < 64; k++) v[k] = v[k] * inv1 * sm[OF_CN + k];
        store_A_row(sm, tid, v);
    }
    __syncthreads();

    int wid = tid >> 5, lane = tid & 31, g = lane >> 2, q = lane & 3;
#pragma unroll
    for (int mt = 0; mt < 2; mt++) {
        int rbase = 32 * wid + 16 * mt;
        float acc[8][4];
        mma_mtile(sm, rbase, g, q, acc);

        // two rows per thread: r0 = rbase+g (c0,c1), r1 = r0+8 (c2,c3)
#pragma unroll
        for (int half = 0; half < 2; half++) {
            int r = rbase + g + 8 * half;
            int nd = blockIdx.x * 128 + r;
            const float* hp = sm + OF_A + r * SA_STR;   // fragment-order row
            float2 z[8];
            float sq2 = 0.f;
#pragma unroll
            for (int nt = 0; nt < 8; nt++) {
                float y0 = fmaxf(acc[nt][2 * half],     0.f);
                float y1 = fmaxf(acc[nt][2 * half + 1], 0.f);
                // h'[8nt+2q] at col' = 16q + nt;  h'[8nt+2q+1] at col' = 16q+8+nt
                float h0 = hp[16 * q + nt];
                float h1 = hp[16 * q + 8 + nt];
                float z0 = h0 + y0, z1 = h1 + y1;
                z[nt] = make_float2(z0, z1);
                sq2 = fmaf(z0, z0, sq2);
                sq2 = fmaf(z1, z1, sq2);
            }
            sq2 += __shfl_xor_sync(0xffffffffu, sq2, 1);
            sq2 += __shfl_xor_sync(0xffffffffu, sq2, 2);
            float inv2 = rsqrtf(sq2 * (1.f / HID) + EPS);
            if (nd < N_NODES) {
                float* orow = out + (size_t)nd * HID + 2 * q;
                const float* hn = sm + OF_HN + 2 * q;
#pragma unroll
                for (int nt = 0; nt < 8; nt++) {
                    *(float2*)(orow + 8 * nt) =
                        make_float2(z[nt].x * inv2 * hn[8 * nt],
                                    z[nt].y * inv2 * hn[8 * nt + 1]);
                }
            }
        }
    }
}

// =====================================================================
extern "C" void kernel_launch(void* const* d_in, const int* in_sizes, int n_in,
                              void* d_out, int out_size)
{
    const float* x         = (const float*)d_in[0];
    const float* conv_w    = (const float*)d_in[1];
    const float* conv_norm = (const float*)d_in[2];
    const float* hid_w     = (const float*)d_in[3];
    const float* hid_norm  = (const float*)d_in[4];
    const int*   row       = (const int*)d_in[5];
    const int*   col       = (const int*)d_in[6];
    float*       out       = (float*)d_out;

    float *mp = nullptr, *ap = nullptr, *hp = nullptr;
    int   *dp = nullptr;
    cudaGetSymbolAddress((void**)&mp, g_m);
    cudaGetSymbolAddress((void**)&ap, g_agg);
    cudaGetSymbolAddress((void**)&hp, g_h);
    cudaGetSymbolAddress((void**)&dp, g_deg);

    cudaFuncSetAttribute(k_conv, cudaFuncAttributeMaxDynamicSharedMemorySize, SMEM_BYTES);
    cudaFuncSetAttribute(k_norm, cudaFuncAttributeMaxDynamicSharedMemorySize, SMEM_BYTES);

    // adjacency buckets: layer-invariant, build once per launch
    cudaMemsetAsync(dp, 0, N_NODES * sizeof(int));
    k_build<<<(N_EDGES + 255) / 256, 256>>>(row, col);

    const int NB = (N_NODES + 127) / 128;
    const int AB = (N_NODES + 15) / 16;

    for (int l = 0; l < N_LAYERS; l++) {
        const float* hsrc = (l == 0) ? x : hp;
        float* hdst = (l == N_LAYERS - 1) ? out : hp;
        k_conv<<<NB, 128, SMEM_BYTES>>>(hsrc, conv_w + l * HID * HID, mp);
        k_agg <<<AB, 256>>>((const float4*)mp, (float4*)ap);
        k_norm<<<NB, 128, SMEM_BYTES>>>(hsrc, ap, hid_w + l * HID * HID,
                                        conv_norm + l * HID, hid_norm + l * HID, hdst);
    }
}

// round 10
// speedup vs baseline: 1.0238x; 1.0238x over previous
#include <cuda_runtime.h>
#include <cstdint>

namespace {
constexpr int N_NODES  = 100000;
constexpr int HID      = 64;
constexpr int N_LAYERS = 4;
constexpr int N_EDGES  = 800000;
constexpr float EPS    = 1e-5f;
constexpr int CAP      = 64;   // bucket capacity (Poisson(8); max deg ~< 40)
constexpr int SA_STR   = 68;   // padded A row stride in floats (17 float4s)
constexpr int WB_STR   = 132;  // padded B thread-row stride in uint32 (33 uint4s)

// dynamic smem layout (float indices)
constexpr int OF_A   = 0;                    // 128 x 68 fp32 (A rows, fragment-order cols)
constexpr int OF_WHI = 128 * SA_STR;         // 32 x 132 uint32 (B hi, per-(g,q) fragment rows)
constexpr int OF_WLO = OF_WHI + 32 * WB_STR; // 32 x 132 uint32 (B lo)
constexpr int OF_CN  = OF_WLO + 32 * WB_STR; // 64 floats
constexpr int OF_HN  = OF_CN + 64;           // 64 floats
constexpr int SMEM_FLOATS = OF_HN + 64;
constexpr int SMEM_BYTES  = SMEM_FLOATS * 4; // 69120 B -> 3 CTAs/SM
}

// Scratch (no cudaMalloc allowed)
__device__ float g_m  [(size_t)N_NODES * HID];
__device__ float g_agg[(size_t)N_NODES * HID];
__device__ float g_h  [(size_t)N_NODES * HID];
__device__ int   g_deg[N_NODES];
__device__ int   g_bkt[(size_t)N_NODES * CAP];

// ---------------- helpers ----------------
__device__ __forceinline__ uint32_t tf32_of(float a) {
    uint32_t r; asm("cvt.rna.tf32.f32 %0, %1;" : "=r"(r) : "f"(a)); return r;
}
__device__ __forceinline__ void mma_tf32(float* c, const uint32_t* a,
                                         uint32_t b0, uint32_t b1) {
    asm volatile(
        "mma.sync.aligned.m16n8k8.row.col.f32.tf32.tf32.f32 "
        "{%0,%1,%2,%3},{%4,%5,%6,%7},{%8,%9},{%0,%1,%2,%3};"
        : "+f"(c[0]), "+f"(c[1]), "+f"(c[2]), "+f"(c[3])
        : "r"(a[0]), "r"(a[1]), "r"(a[2]), "r"(a[3]), "r"(b0), "r"(b1));
}

// A fragment-order column permutation: original k -> col' = 8*(k&7) + (k>>3)

// W split into tf32 hi/lo, stored per-MMA-thread fragment rows:
//   value W[n][k] with n = 8*nt+g, k = 8*ks + q + 4*j  (q<4, j<2)
//   -> smem index (g*4+q)*WB_STR + ks*16 + j*8 + nt
// Reader thread (g,q) then loads, per ks, 4 contiguous uint4 (hi) + 4 (lo).
__device__ __forceinline__ void load_W_split(float* sm, const float* __restrict__ W, int tid) {
    uint32_t* whi = (uint32_t*)(sm + OF_WHI);
    uint32_t* wlo = (uint32_t*)(sm + OF_WLO);
    for (int i = tid; i < HID * HID; i += 128) {
        int n = i >> 6, k = i & 63;
        int g = n & 7, nt = n >> 3;
        int ks = k >> 3, r = k & 7;
        int q = r & 3, j = r >> 2;
        int idx = (g * 4 + q) * WB_STR + ks * 16 + j * 8 + nt;
        float w = __ldg(W + i);
        uint32_t hb = tf32_of(w);
        whi[idx] = hb;
        wlo[idx] = tf32_of(w - __uint_as_float(hb));
    }
}

// store one A row (v[64], natural order) into fragment-order smem row
__device__ __forceinline__ void store_A_row(float* sm, int row, const float* v) {
    float4* dst = (float4*)(sm + OF_A + row * SA_STR);
#pragma unroll
    for (int t = 0; t < 16; t++) {
        int qoff = t >> 1, k0 = ((t & 1) << 5) + qoff;
        dst[t] = make_float4(v[k0], v[k0 + 8], v[k0 + 16], v[k0 + 24]);
    }
}

#define UNPACK8F(dst, a, b) \
    { dst[0]=a.x; dst[1]=a.y; dst[2]=a.z; dst[3]=a.w; \
      dst[4]=b.x; dst[5]=b.y; dst[6]=b.z; dst[7]=b.w; }
#define UNPACK8U(dst, a, b) \
    { dst[0]=a.x; dst[1]=a.y; dst[2]=a.z; dst[3]=a.w; \
      dst[4]=b.x; dst[5]=b.y; dst[6]=b.z; dst[7]=b.w; }

// MMA mainloop for one m-tile (16 rows starting at rbase). acc[nt][4].
// ks-outer / term-outer / nt-inner: consecutive MMAs hit 8 different
// accumulators -> same-acc reuse distance 8 (dependency chains broken).
__device__ __forceinline__ void mma_mtile(const float* sm, int rbase, int g, int q,
                                          float acc[8][4]) {
    // ---- A fragments (fragment-order rows; conflict-free, stride 68) ----
    const float4* Ag  = (const float4*)(sm + OF_A + (rbase + g) * SA_STR);
    const float4* Ag8 = (const float4*)(sm + OF_A + (rbase + g + 8) * SA_STR);
    float4 x0a = Ag [2 * q],     x0b = Ag [2 * q + 1];
    float4 x1a = Ag8[2 * q],     x1b = Ag8[2 * q + 1];
    float4 x2a = Ag [2 * q + 8], x2b = Ag [2 * q + 9];
    float4 x3a = Ag8[2 * q + 8], x3b = Ag8[2 * q + 9];
    float f0[8], f1[8], f2[8], f3[8];
    UNPACK8F(f0, x0a, x0b); UNPACK8F(f1, x1a, x1b);
    UNPACK8F(f2, x2a, x2b); UNPACK8F(f3, x3a, x3b);

    uint32_t ahi[8][4], alo[8][4];
#pragma unroll
    for (int ks = 0; ks < 8; ks++) {
        ahi[ks][0] = tf32_of(f0[ks]); alo[ks][0] = tf32_of(f0[ks] - __uint_as_float(ahi[ks][0]));
        ahi[ks][1] = tf32_of(f1[ks]); alo[ks][1] = tf32_of(f1[ks] - __uint_as_float(ahi[ks][1]));
        ahi[ks][2] = tf32_of(f2[ks]); alo[ks][2] = tf32_of(f2[ks] - __uint_as_float(ahi[ks][2]));
        ahi[ks][3] = tf32_of(f3[ks]); alo[ks][3] = tf32_of(f3[ks] - __uint_as_float(ahi[ks][3]));
    }

#pragma unroll
    for (int nt = 0; nt < 8; nt++)
#pragma unroll
        for (int i = 0; i < 4; i++) acc[nt][i] = 0.f;

    const uint4* Bh = (const uint4*)((const uint32_t*)(sm + OF_WHI) + (g * 4 + q) * WB_STR);
    const uint4* Bl = (const uint4*)((const uint32_t*)(sm + OF_WLO) + (g * 4 + q) * WB_STR);

#pragma unroll
    for (int ks = 0; ks < 8; ks++) {
        uint4 h0 = Bh[4 * ks], h1 = Bh[4 * ks + 1], h2 = Bh[4 * ks + 2], h3 = Bh[4 * ks + 3];
        uint4 l0 = Bl[4 * ks], l1 = Bl[4 * ks + 1], l2 = Bl[4 * ks + 2], l3 = Bl[4 * ks + 3];
        uint32_t bh0[8], bh1[8], bl0[8], bl1[8];
        UNPACK8U(bh0, h0, h1); UNPACK8U(bh1, h2, h3);
        UNPACK8U(bl0, l0, l1); UNPACK8U(bl1, l2, l3);
#pragma unroll
        for (int nt = 0; nt < 8; nt++)
            mma_tf32(acc[nt], ahi[ks], bh0[nt], bh1[nt]);   // hi*hi
#pragma unroll
        for (int nt = 0; nt < 8; nt++)
            mma_tf32(acc[nt], ahi[ks], bl0[nt], bl1[nt]);   // hi*lo
#pragma unroll
        for (int nt = 0; nt < 8; nt++)
            mma_tf32(acc[nt], alo[ks], bh0[nt], bh1[nt]);   // lo*hi
    }
}

// =====================================================================
// Bucket build (once per launch). g_deg memset to 0 first.
// =====================================================================
__global__ void k_build(const int* __restrict__ row, const int* __restrict__ col) {
    int e = blockIdx.x * 256 + threadIdx.x;
    if (e >= N_EDGES) return;
    int r = __ldg(row + e);
    int p = atomicAdd(&g_deg[r], 1);
    if (p < CAP) g_bkt[(size_t)r * CAP + p] = __ldg(col + e);
}

// =====================================================================
// K1: m = relu(h @ Wc^T)  via mma.sync tf32 (3xTF32)
// =====================================================================
__global__ void __launch_bounds__(128, 3) k_conv(
    const float* __restrict__ h, const float* __restrict__ W,
    float* __restrict__ m)
{
    extern __shared__ float sm[];
    int tid = threadIdx.x;

    load_W_split(sm, W, tid);

    int node = blockIdx.x * 128 + tid;
    bool valid = node < N_NODES;
    {
        const float4* hr = (const float4*)(h + (size_t)node * HID);
        float v[64];
#pragma unroll
        for (int c = 0; c < 16; c++) {
            float4 t = valid ? __ldg(hr + c) : make_float4(0.f, 0.f, 0.f, 0.f);
            v[4*c] = t.x; v[4*c+1] = t.y; v[4*c+2] = t.z; v[4*c+3] = t.w;
        }
        store_A_row(sm, tid, v);
    }
    __syncthreads();

    int wid = tid >> 5, lane = tid & 31, g = lane >> 2, q = lane & 3;
#pragma unroll
    for (int mt = 0; mt < 2; mt++) {
        int rbase = 32 * wid + 16 * mt;
        float acc[8][4];
        mma_mtile(sm, rbase, g, q, acc);

        int n0 = blockIdx.x * 128 + rbase + g;
        int n1 = n0 + 8;
        if (n0 < N_NODES) {
            float* mr = m + (size_t)n0 * HID + 2 * q;
#pragma unroll
            for (int nt = 0; nt < 8; nt++)
                *(float2*)(mr + 8 * nt) =
                    make_float2(fmaxf(acc[nt][0], 0.f), fmaxf(acc[nt][1], 0.f));
        }
        if (n1 < N_NODES) {
            float* mr = m + (size_t)n1 * HID + 2 * q;
#pragma unroll
            for (int nt = 0; nt < 8; nt++)
                *(float2*)(mr + 8 * nt) =
                    make_float2(fmaxf(acc[nt][2], 0.f), fmaxf(acc[nt][3], 0.f));
        }
    }
}

// =====================================================================
// K2: agg[r] = sum_{e: row[e]=r} m[col[e]]  — gather, 16 lanes/node
// =====================================================================
__global__ void __launch_bounds__(256) k_agg(
    const float4* __restrict__ m, float4* __restrict__ agg)
{
    int wid  = threadIdx.x >> 5;
    int lane = threadIdx.x & 31;
    int node = (blockIdx.x * 8 + wid) * 2 + (lane >> 4);
    if (node >= N_NODES) return;
    int l = lane & 15;

    int d = g_deg[node]; if (d > CAP) d = CAP;
    const int* bp = g_bkt + (size_t)node * CAP;

    float4 acc = make_float4(0.f, 0.f, 0.f, 0.f);
    int i = 0;
    for (; i + 2 <= d; i += 2) {
        int c0 = __ldg(bp + i);
        int c1 = __ldg(bp + i + 1);
        float4 v0 = __ldg(m + (size_t)c0 * 16 + l);
        float4 v1 = __ldg(m + (size_t)c1 * 16 + l);
        acc.x += v0.x + v1.x; acc.y += v0.y + v1.y;
        acc.z += v0.z + v1.z; acc.w += v0.w + v1.w;
    }
    if (i < d) {
        int c = __ldg(bp + i);
        float4 v = __ldg(m + (size_t)c * 16 + l);
        acc.x += v.x; acc.y += v.y; acc.z += v.z; acc.w += v.w;
    }
    agg[(size_t)node * 16 + l] = acc;
}

// =====================================================================
// K3: h' = rmsnorm(h+agg)*cnw;  y = relu(h' @ Wh^T)  (mma.sync 3xTF32);
//     out = rmsnorm(h'+y)*hnw
// =====================================================================
__global__ void __launch_bounds__(128, 3) k_norm(
    const float* __restrict__ h, const float* __restrict__ agg,
    const float* __restrict__ W, const float* __restrict__ cnw,
    const float* __restrict__ hnw, float* __restrict__ out)
{
    extern __shared__ float sm[];
    int tid = threadIdx.x;

    if (tid < HID) {
        sm[OF_CN + tid] = __ldg(cnw + tid);
        sm[OF_HN + tid] = __ldg(hnw + tid);
    }
    load_W_split(sm, W, tid);
    __syncthreads();

    int node = blockIdx.x * 128 + tid;
    bool valid = node < N_NODES;
    {
        const float4* hr = (const float4*)(h   + (size_t)node * HID);
        const float4* ar = (const float4*)(agg + (size_t)node * HID);
        float v[64];
        float sq = 0.f;
#pragma unroll
        for (int c = 0; c < 16; c++) {
            float4 a = valid ? __ldg(hr + c) : make_float4(0.f, 0.f, 0.f, 0.f);
            float4 b = valid ? __ldg(ar + c) : make_float4(0.f, 0.f, 0.f, 0.f);
            float z0 = a.x + b.x, z1 = a.y + b.y, z2 = a.z + b.z, z3 = a.w + b.w;
            v[4*c] = z0; v[4*c+1] = z1; v[4*c+2] = z2; v[4*c+3] = z3;
            sq = fmaf(z0, z0, sq); sq = fmaf(z1, z1, sq);
            sq = fmaf(z2, z2, sq); sq = fmaf(z3, z3, sq);
        }
        float inv1 = rsqrtf(sq * (1.f / HID) + EPS);
#pragma unroll
        for (int k = 0; k < 64; k++) v[k] = v[k] * inv1 * sm[OF_CN + k];
        store_A_row(sm, tid, v);
    }
    __syncthreads();

    int wid = tid >> 5, lane = tid & 31, g = lane >> 2, q = lane & 3;
#pragma unroll
    for (int mt = 0; mt < 2; mt++) {
        int rbase = 32 * wid + 16 * mt;
        float acc[8][4];
        mma_mtile(sm, rbase, g, q, acc);

        // two rows per thread: r0 = rbase+g (c0,c1), r1 = r0+8 (c2,c3)
#pragma unroll
        for (int half = 0; half < 2; half++) {
            int r = rbase + g + 8 * half;
            int nd = blockIdx.x * 128 + r;
            const float* hp = sm + OF_A + r * SA_STR;   // fragment-order row
            float2 z[8];
            float sq2 = 0.f;
#pragma unroll
            for (int nt = 0; nt < 8; nt++) {
                float y0 = fmaxf(acc[nt][2 * half],     0.f);
                float y1 = fmaxf(acc[nt][2 * half + 1], 0.f);
                float h0 = hp[16 * q + nt];        // h'[8nt+2q]
                float h1 = hp[16 * q + 8 + nt];    // h'[8nt+2q+1]
                float z0 = h0 + y0, z1 = h1 + y1;
                z[nt] = make_float2(z0, z1);
                sq2 = fmaf(z0, z0, sq2);
                sq2 = fmaf(z1, z1, sq2);
            }
            sq2 += __shfl_xor_sync(0xffffffffu, sq2, 1);
            sq2 += __shfl_xor_sync(0xffffffffu, sq2, 2);
            float inv2 = rsqrtf(sq2 * (1.f / HID) + EPS);
            if (nd < N_NODES) {
                float* orow = out + (size_t)nd * HID + 2 * q;
                const float* hn = sm + OF_HN + 2 * q;
#pragma unroll
                for (int nt = 0; nt < 8; nt++) {
                    *(float2*)(orow + 8 * nt) =
                        make_float2(z[nt].x * inv2 * hn[8 * nt],
                                    z[nt].y * inv2 * hn[8 * nt + 1]);
                }
            }
        }
    }
}

// =====================================================================
extern "C" void kernel_launch(void* const* d_in, const int* in_sizes, int n_in,
                              void* d_out, int out_size)
{
    const float* x         = (const float*)d_in[0];
    const float* conv_w    = (const float*)d_in[1];
    const float* conv_norm = (const float*)d_in[2];
    const float* hid_w     = (const float*)d_in[3];
    const float* hid_norm  = (const float*)d_in[4];
    const int*   row       = (const int*)d_in[5];
    const int*   col       = (const int*)d_in[6];
    float*       out       = (float*)d_out;

    float *mp = nullptr, *ap = nullptr, *hp = nullptr;
    int   *dp = nullptr;
    cudaGetSymbolAddress((void**)&mp, g_m);
    cudaGetSymbolAddress((void**)&ap, g_agg);
    cudaGetSymbolAddress((void**)&hp, g_h);
    cudaGetSymbolAddress((void**)&dp, g_deg);

    cudaFuncSetAttribute(k_conv, cudaFuncAttributeMaxDynamicSharedMemorySize, SMEM_BYTES);
    cudaFuncSetAttribute(k_norm, cudaFuncAttributeMaxDynamicSharedMemorySize, SMEM_BYTES);

    // adjacency buckets: layer-invariant, build once per launch
    cudaMemsetAsync(dp, 0, N_NODES * sizeof(int));
    k_build<<<(N_EDGES + 255) / 256, 256>>>(row, col);

    const int NB = (N_NODES + 127) / 128;
    const int AB = (N_NODES + 15) / 16;

    for (int l = 0; l < N_LAYERS; l++) {
        const float* hsrc = (l == 0) ? x : hp;
        float* hdst = (l == N_LAYERS - 1) ? out : hp;
        k_conv<<<NB, 128, SMEM_BYTES>>>(hsrc, conv_w + l * HID * HID, mp);
        k_agg <<<AB, 256>>>((const float4*)mp, (float4*)ap);
        k_norm<<<NB, 128, SMEM_BYTES>>>(hsrc, ap, hid_w + l * HID * HID,
                                        conv_norm + l * HID, hid_norm + l * HID, hdst);
    }
}

// round 11
// speedup vs baseline: 1.1786x; 1.1512x over previous
#include <cuda_runtime.h>
#include <cuda_fp16.h>
#include <cstdint>

namespace {
constexpr int N_NODES  = 100000;
constexpr int HID      = 64;
constexpr int N_LAYERS = 4;
constexpr int N_EDGES  = 800000;
constexpr float EPS    = 1e-5f;
constexpr int CAP      = 64;    // bucket capacity (Poisson(8))
constexpr int SA_STR   = 72;    // A row stride in floats (18 float4s; frag loads conflict-free)
constexpr float LO_SCALE   = 2048.f;        // 2^11
constexpr float LO_INV     = 1.f / 2048.f;

// dynamic smem layout (byte offsets)
constexpr int OF_A    = 0;                       // 128 x 72 fp32
constexpr int WROW    = 272;                     // 68 uint32 per (g,q) fragment row
constexpr int OF_WHI  = 128 * SA_STR * 4;        // 36864
constexpr int OF_WLO  = OF_WHI + 32 * WROW;      // 45568
constexpr int OF_CN   = OF_WLO + 32 * WROW;      // 54272
constexpr int OF_HN   = OF_CN + 256;             // 54528
constexpr int SMEM_BYTES = OF_HN + 256;          // 54784 -> 4 CTAs/SM
}

// Scratch (no cudaMalloc allowed)
__device__ float g_m  [(size_t)N_NODES * HID];
__device__ float g_agg[(size_t)N_NODES * HID];
__device__ float g_h  [(size_t)N_NODES * HID];
__device__ int   g_deg[N_NODES];
__device__ int   g_bkt[(size_t)N_NODES * CAP];

// ---------------- helpers ----------------
__device__ __forceinline__ uint32_t pack_h2(float x, float y) {
    __half2 h = __floats2half2_rn(x, y);
    return *reinterpret_cast<uint32_t*>(&h);
}
__device__ __forceinline__ void mma_f16(float* c, const uint32_t* a,
                                        uint32_t b0, uint32_t b1) {
    asm volatile(
        "mma.sync.aligned.m16n8k16.row.col.f32.f16.f16.f32 "
        "{%0,%1,%2,%3},{%4,%5,%6,%7},{%8,%9},{%0,%1,%2,%3};"
        : "+f"(c[0]), "+f"(c[1]), "+f"(c[2]), "+f"(c[3])
        : "r"(a[0]), "r"(a[1]), "r"(a[2]), "r"(a[3]), "r"(b0), "r"(b1));
}

// W[n][k] split into fp16 hi + scaled lo, stored as per-(g,q)-thread fragment
// rows: n = 8*nt+g; k = 16*ks + 8*j + 2*q + s  ->
//   uint32 idx = (4g+q)*68 + ks*16 + j*8 + nt, half s within the uint32.
__device__ __forceinline__ void load_W_split(char* smem, const float* __restrict__ W,
                                             int tid) {
    uint16_t* whi = (uint16_t*)(smem + OF_WHI);
    uint16_t* wlo = (uint16_t*)(smem + OF_WLO);
    for (int i = tid; i < HID * HID; i += 128) {
        int n = i >> 6, k = i & 63;
        int g = n & 7, nt = n >> 3;
        int ks = k >> 4, j = (k >> 3) & 1, q = (k & 7) >> 1, s = k & 1;
        int hidx = ((g * 4 + q) * 68 + ks * 16 + j * 8 + nt) * 2 + s;
        float w = __ldg(W + i);
        __half hh = __float2half_rn(w);
        whi[hidx] = *reinterpret_cast<uint16_t*>(&hh);
        __half hl = __float2half_rn((w - __half2float(hh)) * LO_SCALE);
        wlo[hidx] = *reinterpret_cast<uint16_t*>(&hl);
    }
}

#define UNPACK8U(dst, a, b) \
    { dst[0]=a.x; dst[1]=a.y; dst[2]=a.z; dst[3]=a.w; \
      dst[4]=b.x; dst[5]=b.y; dst[6]=b.z; dst[7]=b.w; }

// split one float2 into packed fp16 hi and packed scaled lo
__device__ __forceinline__ void split_pair(float2 p, uint32_t& hi, uint32_t& lo) {
    hi = pack_h2(p.x, p.y);
    __half2 h = *reinterpret_cast<__half2*>(&hi);
    lo = pack_h2((p.x - __low2float(h))  * LO_SCALE,
                 (p.y - __high2float(h)) * LO_SCALE);
}

// MMA mainloop for one 16-row m-tile.  acc = hi*hi terms, acc2 = scaled cross
// terms; final y = acc + acc2 * LO_INV.
__device__ __forceinline__ void mma_mtile(const char* smem, int rbase, int g, int q,
                                          float acc[8][4], float acc2[8][4]) {
#pragma unroll
    for (int nt = 0; nt < 8; nt++)
#pragma unroll
        for (int i = 0; i < 4; i++) { acc[nt][i] = 0.f; acc2[nt][i] = 0.f; }

    const float* Ar0 = (const float*)smem + (rbase + g) * SA_STR;
    const float* Ar1 = Ar0 + 8 * SA_STR;
    const uint4* Bh = (const uint4*)(smem + OF_WHI + (g * 4 + q) * WROW);
    const uint4* Bl = (const uint4*)(smem + OF_WLO + (g * 4 + q) * WROW);

#pragma unroll
    for (int ks = 0; ks < 4; ks++) {
        // A fragments: rows g,g+8; k-pairs (2q, 2q+1) and (2q+8, 2q+9)
        uint32_t ahi[4], alo[4];
        split_pair(*(const float2*)(Ar0 + 16 * ks + 2 * q),     ahi[0], alo[0]);
        split_pair(*(const float2*)(Ar1 + 16 * ks + 2 * q),     ahi[1], alo[1]);
        split_pair(*(const float2*)(Ar0 + 16 * ks + 8 + 2 * q), ahi[2], alo[2]);
        split_pair(*(const float2*)(Ar1 + 16 * ks + 8 + 2 * q), ahi[3], alo[3]);

        uint4 h0 = Bh[4 * ks], h1 = Bh[4 * ks + 1], h2 = Bh[4 * ks + 2], h3 = Bh[4 * ks + 3];
        uint4 l0 = Bl[4 * ks], l1 = Bl[4 * ks + 1], l2 = Bl[4 * ks + 2], l3 = Bl[4 * ks + 3];
        uint32_t bh0[8], bh1[8], bl0[8], bl1[8];
        UNPACK8U(bh0, h0, h1); UNPACK8U(bh1, h2, h3);
        UNPACK8U(bl0, l0, l1); UNPACK8U(bl1, l2, l3);

#pragma unroll
        for (int nt = 0; nt < 8; nt++)
            mma_f16(acc[nt],  ahi, bh0[nt], bh1[nt]);   // hi*hi
#pragma unroll
        for (int nt = 0; nt < 8; nt++)
            mma_f16(acc2[nt], ahi, bl0[nt], bl1[nt]);   // hi*lo  (scaled)
#pragma unroll
        for (int nt = 0; nt < 8; nt++)
            mma_f16(acc2[nt], alo, bh0[nt], bh1[nt]);   // lo*hi  (scaled)
    }
}

// =====================================================================
// Bucket build (once per launch). g_deg memset to 0 first.
// =====================================================================
__global__ void k_build(const int* __restrict__ row, const int* __restrict__ col) {
    int e = blockIdx.x * 256 + threadIdx.x;
    if (e >= N_EDGES) return;
    int r = __ldg(row + e);
    int p = atomicAdd(&g_deg[r], 1);
    if (p < CAP) g_bkt[(size_t)r * CAP + p] = __ldg(col + e);
}

// =====================================================================
// K1: m = relu(h @ Wc^T)   (fp16 2-split mma.sync)
// =====================================================================
__global__ void __launch_bounds__(128, 4) k_conv(
    const float* __restrict__ h, const float* __restrict__ W,
    float* __restrict__ m)
{
    extern __shared__ char smem[];
    float* smA = (float*)smem;
    int tid = threadIdx.x;

    load_W_split(smem, W, tid);

    int node = blockIdx.x * 128 + tid;
    bool valid = node < N_NODES;
    {
        const float4* hr = (const float4*)(h + (size_t)node * HID);
        float4* dst = (float4*)(smA + tid * SA_STR);
#pragma unroll
        for (int c = 0; c < 16; c++)
            dst[c] = valid ? __ldg(hr + c) : make_float4(0.f, 0.f, 0.f, 0.f);
    }
    __syncthreads();

    int wid = tid >> 5, lane = tid & 31, g = lane >> 2, q = lane & 3;
#pragma unroll
    for (int mt = 0; mt < 2; mt++) {
        int rbase = 32 * wid + 16 * mt;
        float acc[8][4], acc2[8][4];
        mma_mtile(smem, rbase, g, q, acc, acc2);

        int n0 = blockIdx.x * 128 + rbase + g;
        int n1 = n0 + 8;
        if (n0 < N_NODES) {
            float* mr = m + (size_t)n0 * HID + 2 * q;
#pragma unroll
            for (int nt = 0; nt < 8; nt++) {
                float y0 = acc[nt][0] + acc2[nt][0] * LO_INV;
                float y1 = acc[nt][1] + acc2[nt][1] * LO_INV;
                *(float2*)(mr + 8 * nt) = make_float2(fmaxf(y0, 0.f), fmaxf(y1, 0.f));
            }
        }
        if (n1 < N_NODES) {
            float* mr = m + (size_t)n1 * HID + 2 * q;
#pragma unroll
            for (int nt = 0; nt < 8; nt++) {
                float y0 = acc[nt][2] + acc2[nt][2] * LO_INV;
                float y1 = acc[nt][3] + acc2[nt][3] * LO_INV;
                *(float2*)(mr + 8 * nt) = make_float2(fmaxf(y0, 0.f), fmaxf(y1, 0.f));
            }
        }
    }
}

// =====================================================================
// K2: agg[r] = sum m[col] over in-neighbors — gather, 16 lanes/node
// =====================================================================
__global__ void __launch_bounds__(256) k_agg(
    const float4* __restrict__ m, float4* __restrict__ agg)
{
    int wid  = threadIdx.x >> 5;
    int lane = threadIdx.x & 31;
    int node = (blockIdx.x * 8 + wid) * 2 + (lane >> 4);
    if (node >= N_NODES) return;
    int l = lane & 15;

    int d = g_deg[node]; if (d > CAP) d = CAP;
    const int* bp = g_bkt + (size_t)node * CAP;

    float4 acc = make_float4(0.f, 0.f, 0.f, 0.f);
    int i = 0;
    for (; i + 2 <= d; i += 2) {
        int c0 = __ldg(bp + i);
        int c1 = __ldg(bp + i + 1);
        float4 v0 = __ldg(m + (size_t)c0 * 16 + l);
        float4 v1 = __ldg(m + (size_t)c1 * 16 + l);
        acc.x += v0.x + v1.x; acc.y += v0.y + v1.y;
        acc.z += v0.z + v1.z; acc.w += v0.w + v1.w;
    }
    if (i < d) {
        int c = __ldg(bp + i);
        float4 v = __ldg(m + (size_t)c * 16 + l);
        acc.x += v.x; acc.y += v.y; acc.z += v.z; acc.w += v.w;
    }
    agg[(size_t)node * 16 + l] = acc;
}

// =====================================================================
// K3: h' = rmsnorm(h+agg)*cnw;  y = relu(h' @ Wh^T);  out = rmsnorm(h'+y)*hnw
// =====================================================================
__global__ void __launch_bounds__(128, 4) k_norm(
    const float* __restrict__ h, const float* __restrict__ agg,
    const float* __restrict__ W, const float* __restrict__ cnw,
    const float* __restrict__ hnw, float* __restrict__ out)
{
    extern __shared__ char smem[];
    float* smA = (float*)smem;
    float* cn  = (float*)(smem + OF_CN);
    float* hn  = (float*)(smem + OF_HN);
    int tid = threadIdx.x;

    if (tid < HID) {
        cn[tid] = __ldg(cnw + tid);
        hn[tid] = __ldg(hnw + tid);
    }
    load_W_split(smem, W, tid);
    __syncthreads();

    int node = blockIdx.x * 128 + tid;
    bool valid = node < N_NODES;
    {
        const float4* hr = (const float4*)(h   + (size_t)node * HID);
        const float4* ar = (const float4*)(agg + (size_t)node * HID);
        float v[64];
        float sq = 0.f;
#pragma unroll
        for (int c = 0; c < 16; c++) {
            float4 a = valid ? __ldg(hr + c) : make_float4(0.f, 0.f, 0.f, 0.f);
            float4 b = valid ? __ldg(ar + c) : make_float4(0.f, 0.f, 0.f, 0.f);
            float z0 = a.x + b.x, z1 = a.y + b.y, z2 = a.z + b.z, z3 = a.w + b.w;
            v[4*c] = z0; v[4*c+1] = z1; v[4*c+2] = z2; v[4*c+3] = z3;
            sq = fmaf(z0, z0, sq); sq = fmaf(z1, z1, sq);
            sq = fmaf(z2, z2, sq); sq = fmaf(z3, z3, sq);
        }
        float inv1 = rsqrtf(sq * (1.f / HID) + EPS);
        float4* dst = (float4*)(smA + tid * SA_STR);
#pragma unroll
        for (int c = 0; c < 16; c++) {
            dst[c] = make_float4(v[4*c]   * inv1 * cn[4*c],
                                 v[4*c+1] * inv1 * cn[4*c+1],
                                 v[4*c+2] * inv1 * cn[4*c+2],
                                 v[4*c+3] * inv1 * cn[4*c+3]);
        }
    }
    __syncthreads();

    int wid = tid >> 5, lane = tid & 31, g = lane >> 2, q = lane & 3;
#pragma unroll
    for (int mt = 0; mt < 2; mt++) {
        int rbase = 32 * wid + 16 * mt;
        float acc[8][4], acc2[8][4];
        mma_mtile(smem, rbase, g, q, acc, acc2);

        // two rows per thread: r0 = rbase+g (c0,c1), r1 = r0+8 (c2,c3)
#pragma unroll
        for (int half = 0; half < 2; half++) {
            int r = rbase + g + 8 * half;
            int nd = blockIdx.x * 128 + r;
            const float* hp = smA + r * SA_STR;   // natural-order h' row
            float2 z[8];
            float sq2 = 0.f;
#pragma unroll
            for (int nt = 0; nt < 8; nt++) {
                float y0 = acc[nt][2 * half]     + acc2[nt][2 * half]     * LO_INV;
                float y1 = acc[nt][2 * half + 1] + acc2[nt][2 * half + 1] * LO_INV;
                float2 hv = *(const float2*)(hp + 8 * nt + 2 * q);
                float z0 = hv.x + fmaxf(y0, 0.f);
                float z1 = hv.y + fmaxf(y1, 0.f);
                z[nt] = make_float2(z0, z1);
                sq2 = fmaf(z0, z0, sq2);
                sq2 = fmaf(z1, z1, sq2);
            }
            sq2 += __shfl_xor_sync(0xffffffffu, sq2, 1);
            sq2 += __shfl_xor_sync(0xffffffffu, sq2, 2);
            float inv2 = rsqrtf(sq2 * (1.f / HID) + EPS);
            if (nd < N_NODES) {
                float* orow = out + (size_t)nd * HID + 2 * q;
#pragma unroll
                for (int nt = 0; nt < 8; nt++) {
                    *(float2*)(orow + 8 * nt) =
                        make_float2(z[nt].x * inv2 * hn[8 * nt + 2 * q],
                                    z[nt].y * inv2 * hn[8 * nt + 2 * q + 1]);
                }
            }
        }
    }
}

// =====================================================================
extern "C" void kernel_launch(void* const* d_in, const int* in_sizes, int n_in,
                              void* d_out, int out_size)
{
    const float* x         = (const float*)d_in[0];
    const float* conv_w    = (const float*)d_in[1];
    const float* conv_norm = (const float*)d_in[2];
    const float* hid_w     = (const float*)d_in[3];
    const float* hid_norm  = (const float*)d_in[4];
    const int*   row       = (const int*)d_in[5];
    const int*   col       = (const int*)d_in[6];
    float*       out       = (float*)d_out;

    float *mp = nullptr, *ap = nullptr, *hp = nullptr;
    int   *dp = nullptr;
    cudaGetSymbolAddress((void**)&mp, g_m);
    cudaGetSymbolAddress((void**)&ap, g_agg);
    cudaGetSymbolAddress((void**)&hp, g_h);
    cudaGetSymbolAddress((void**)&dp, g_deg);

    cudaFuncSetAttribute(k_conv, cudaFuncAttributeMaxDynamicSharedMemorySize, SMEM_BYTES);
    cudaFuncSetAttribute(k_norm, cudaFuncAttributeMaxDynamicSharedMemorySize, SMEM_BYTES);

    // adjacency buckets: layer-invariant, build once per launch
    cudaMemsetAsync(dp, 0, N_NODES * sizeof(int));
    k_build<<<(N_EDGES + 255) / 256, 256>>>(row, col);

    const int NB = (N_NODES + 127) / 128;
    const int AB = (N_NODES + 15) / 16;

    for (int l = 0; l < N_LAYERS; l++) {
        const float* hsrc = (l == 0) ? x : hp;
        float* hdst = (l == N_LAYERS - 1) ? out : hp;
        k_conv<<<NB, 128, SMEM_BYTES>>>(hsrc, conv_w + l * HID * HID, mp);
        k_agg <<<AB, 256>>>((const float4*)mp, (float4*)ap);
        k_norm<<<NB, 128, SMEM_BYTES>>>(hsrc, ap, hid_w + l * HID * HID,
                                        conv_norm + l * HID, hid_norm + l * HID, hdst);
    }
}

// round 12
// speedup vs baseline: 1.2073x; 1.0244x over previous
#include <cuda_runtime.h>
#include <cuda_fp16.h>
#include <cstdint>

namespace {
constexpr int N_NODES  = 100000;
constexpr int HID      = 64;
constexpr int N_LAYERS = 4;
constexpr int N_EDGES  = 800000;
constexpr float EPS    = 1e-5f;
constexpr int CAP      = 64;
constexpr float LO_SCALE = 2048.f;    // 2^11
constexpr float LO_INV   = 1.f / 2048.f;

// dynamic smem layout (byte offsets)
// A tile: 128 rows x 32 uint32 (packed half2 k-pairs), XOR-swizzled
constexpr int OF_AHI = 0;            // 16384 B
constexpr int OF_ALO = 16384;        // 16384 B
constexpr int OF_WHI = 32768;        // 32 x 68 uint32 = 8704 B
constexpr int OF_WLO = 41472;        // 8704 B
constexpr int OF_CN  = 50176;        // 256 B
constexpr int OF_HN  = 50432;        // 256 B
constexpr int SMEM_BYTES = 50688;    // <= 57344 -> 4 CTAs/SM
}

// Scratch (no cudaMalloc allowed)
__device__ float g_m  [(size_t)N_NODES * HID];
__device__ float g_agg[(size_t)N_NODES * HID];
__device__ float g_h  [(size_t)N_NODES * HID];
__device__ int   g_deg[N_NODES];
__device__ int   g_bkt[(size_t)N_NODES * CAP];

// ---------------- helpers ----------------
__device__ __forceinline__ uint32_t pack_h2(float x, float y) {
    __half2 h = __floats2half2_rn(x, y);
    return *reinterpret_cast<uint32_t*>(&h);
}
__device__ __forceinline__ float2 h2f2(uint32_t u) {
    __half2 h = *reinterpret_cast<__half2*>(&u);
    return __half22float2(h);
}
__device__ __forceinline__ void mma_f16(float* c, const uint32_t* a,
                                        uint32_t b0, uint32_t b1) {
    asm volatile(
        "mma.sync.aligned.m16n8k16.row.col.f32.f16.f16.f32 "
        "{%0,%1,%2,%3},{%4,%5,%6,%7},{%8,%9},{%0,%1,%2,%3};"
        : "+f"(c[0]), "+f"(c[1]), "+f"(c[2]), "+f"(c[3])
        : "r"(a[0]), "r"(a[1]), "r"(a[2]), "r"(a[3]), "r"(b0), "r"(b1));
}

#define UNPACK8U(dst, a, b) \
    { dst[0]=a.x; dst[1]=a.y; dst[2]=a.z; dst[3]=a.w; \
      dst[4]=b.x; dst[5]=b.y; dst[6]=b.z; dst[7]=b.w; }

// W[n][k] -> fp16 hi + scaled lo fragment rows (same mapping as round 11):
// n = 8*nt+g; k = 16*ks+8*j+2*q+s -> uint32 idx (4g+q)*68 + ks*16 + j*8 + nt.
__device__ __forceinline__ void load_W_split(char* smem, const float* __restrict__ W,
                                             int tid) {
    uint16_t* whi = (uint16_t*)(smem + OF_WHI);
    uint16_t* wlo = (uint16_t*)(smem + OF_WLO);
    for (int i = tid; i < HID * HID; i += 128) {
        int n = i >> 6, k = i & 63;
        int g = n & 7, nt = n >> 3;
        int ks = k >> 4, j = (k >> 3) & 1, q = (k & 7) >> 1, s = k & 1;
        int hidx = ((g * 4 + q) * 68 + ks * 16 + j * 8 + nt) * 2 + s;
        float w = __ldg(W + i);
        __half hh = __float2half_rn(w);
        whi[hidx] = *reinterpret_cast<uint16_t*>(&hh);
        __half hl = __float2half_rn((w - __half2float(hh)) * LO_SCALE);
        wlo[hidx] = *reinterpret_cast<uint16_t*>(&hl);
    }
}

// split v[64] (one node row) into packed hi/lo half2 and store into A tile.
// uint32 col for k-pair p: p ^ ((r&7)<<2); vectorized as uint4 col c ^ (r&7).
__device__ __forceinline__ void store_A_split(char* smem, int r, const float* v) {
    uint4* Ah = (uint4*)(smem + OF_AHI) + r * 8;
    uint4* Al = (uint4*)(smem + OF_ALO) + r * 8;
    int sw = r & 7;
#pragma unroll
    for (int c = 0; c < 8; c++) {
        uint4 hi, lo;
        uint32_t* hp = &hi.x;
        uint32_t* lp = &lo.x;
#pragma unroll
        for (int i = 0; i < 4; i++) {
            float x = v[8 * c + 2 * i], y = v[8 * c + 2 * i + 1];
            uint32_t h = pack_h2(x, y);
            float2 hf = h2f2(h);
            hp[i] = h;
            lp[i] = pack_h2((x - hf.x) * LO_SCALE, (y - hf.y) * LO_SCALE);
        }
        Ah[c ^ sw] = hi;
        Al[c ^ sw] = lo;
    }
}

// MMA mainloop for one 16-row m-tile from pre-split A. acc=hi*hi, acc2=cross(scaled).
__device__ __forceinline__ void mma_mtile(const char* smem, int rbase, int g, int q,
                                          float acc[8][4], float acc2[8][4]) {
#pragma unroll
    for (int nt = 0; nt < 8; nt++)
#pragma unroll
        for (int i = 0; i < 4; i++) { acc[nt][i] = 0.f; acc2[nt][i] = 0.f; }

    const uint32_t* Ah = (const uint32_t*)(smem + OF_AHI);
    const uint32_t* Al = (const uint32_t*)(smem + OF_ALO);
    int r0 = rbase + g, r1 = r0 + 8;
    int sw = (r0 & 7) << 2;
    const uint4* Bh = (const uint4*)(smem + OF_WHI) + (g * 4 + q) * 17;
    const uint4* Bl = (const uint4*)(smem + OF_WLO) + (g * 4 + q) * 17;

#pragma unroll
    for (int ks = 0; ks < 4; ks++) {
        int p0 = (8 * ks + q) ^ sw;
        int p1 = (8 * ks + q + 4) ^ sw;
        uint32_t ahi[4], alo[4];
        ahi[0] = Ah[r0 * 32 + p0]; ahi[1] = Ah[r1 * 32 + p0];
        ahi[2] = Ah[r0 * 32 + p1]; ahi[3] = Ah[r1 * 32 + p1];
        alo[0] = Al[r0 * 32 + p0]; alo[1] = Al[r1 * 32 + p0];
        alo[2] = Al[r0 * 32 + p1]; alo[3] = Al[r1 * 32 + p1];

        uint4 h0 = Bh[4*ks], h1 = Bh[4*ks+1], h2 = Bh[4*ks+2], h3 = Bh[4*ks+3];
        uint4 l0 = Bl[4*ks], l1 = Bl[4*ks+1], l2 = Bl[4*ks+2], l3 = Bl[4*ks+3];
        uint32_t bh0[8], bh1[8], bl0[8], bl1[8];
        UNPACK8U(bh0, h0, h1); UNPACK8U(bh1, h2, h3);
        UNPACK8U(bl0, l0, l1); UNPACK8U(bl1, l2, l3);

#pragma unroll
        for (int nt = 0; nt < 8; nt++)
            mma_f16(acc[nt],  ahi, bh0[nt], bh1[nt]);
#pragma unroll
        for (int nt = 0; nt < 8; nt++)
            mma_f16(acc2[nt], ahi, bl0[nt], bl1[nt]);
#pragma unroll
        for (int nt = 0; nt < 8; nt++)
            mma_f16(acc2[nt], alo, bh0[nt], bh1[nt]);
    }
}

// =====================================================================
// Bucket build (once per launch). g_deg memset to 0 first.
// =====================================================================
__global__ void k_build(const int* __restrict__ row, const int* __restrict__ col) {
    int e = blockIdx.x * 256 + threadIdx.x;
    if (e >= N_EDGES) return;
    int r = __ldg(row + e);
    int p = atomicAdd(&g_deg[r], 1);
    if (p < CAP) g_bkt[(size_t)r * CAP + p] = __ldg(col + e);
}

// =====================================================================
// K0: m = relu(x @ Wc0^T)   (layer-0 conv only)
// =====================================================================
__global__ void __launch_bounds__(128, 4) k_conv0(
    const float* __restrict__ h, const float* __restrict__ W,
    float* __restrict__ m)
{
    extern __shared__ char smem[];
    int tid = threadIdx.x;

    load_W_split(smem, W, tid);

    int node = blockIdx.x * 128 + tid;
    bool valid = node < N_NODES;
    {
        const float4* hr = (const float4*)(h + (size_t)node * HID);
        float v[64];
#pragma unroll
        for (int c = 0; c < 16; c++) {
            float4 t = valid ? __ldg(hr + c) : make_float4(0.f, 0.f, 0.f, 0.f);
            v[4*c] = t.x; v[4*c+1] = t.y; v[4*c+2] = t.z; v[4*c+3] = t.w;
        }
        store_A_split(smem, tid, v);
    }
    __syncthreads();

    int wid = tid >> 5, lane = tid & 31, g = lane >> 2, q = lane & 3;
#pragma unroll
    for (int mt = 0; mt < 2; mt++) {
        int rbase = 32 * wid + 16 * mt;
        float acc[8][4], acc2[8][4];
        mma_mtile(smem, rbase, g, q, acc, acc2);

        int n0 = blockIdx.x * 128 + rbase + g;
        int n1 = n0 + 8;
        if (n0 < N_NODES) {
            float* mr = m + (size_t)n0 * HID + 2 * q;
#pragma unroll
            for (int nt = 0; nt < 8; nt++) {
                float y0 = acc[nt][0] + acc2[nt][0] * LO_INV;
                float y1 = acc[nt][1] + acc2[nt][1] * LO_INV;
                *(float2*)(mr + 8 * nt) = make_float2(fmaxf(y0, 0.f), fmaxf(y1, 0.f));
            }
        }
        if (n1 < N_NODES) {
            float* mr = m + (size_t)n1 * HID + 2 * q;
#pragma unroll
            for (int nt = 0; nt < 8; nt++) {
                float y0 = acc[nt][2] + acc2[nt][2] * LO_INV;
                float y1 = acc[nt][3] + acc2[nt][3] * LO_INV;
                *(float2*)(mr + 8 * nt) = make_float2(fmaxf(y0, 0.f), fmaxf(y1, 0.f));
            }
        }
    }
}

// =====================================================================
// K2: agg[r] = sum m[col] over in-neighbors — gather, 16 lanes/node
// =====================================================================
__global__ void __launch_bounds__(256) k_agg(
    const float4* __restrict__ m, float4* __restrict__ agg)
{
    int wid  = threadIdx.x >> 5;
    int lane = threadIdx.x & 31;
    int node = (blockIdx.x * 8 + wid) * 2 + (lane >> 4);
    if (node >= N_NODES) return;
    int l = lane & 15;

    int d = g_deg[node]; if (d > CAP) d = CAP;
    const int* bp = g_bkt + (size_t)node * CAP;

    float4 acc = make_float4(0.f, 0.f, 0.f, 0.f);
    int i = 0;
    for (; i + 2 <= d; i += 2) {
        int c0 = __ldg(bp + i);
        int c1 = __ldg(bp + i + 1);
        float4 v0 = __ldg(m + (size_t)c0 * 16 + l);
        float4 v1 = __ldg(m + (size_t)c1 * 16 + l);
        acc.x += v0.x + v1.x; acc.y += v0.y + v1.y;
        acc.z += v0.z + v1.z; acc.w += v0.w + v1.w;
    }
    if (i < d) {
        int c = __ldg(bp + i);
        float4 v = __ldg(m + (size_t)c * 16 + l);
        acc.x += v.x; acc.y += v.y; acc.z += v.z; acc.w += v.w;
    }
    agg[(size_t)node * 16 + l] = acc;
}

// =====================================================================
// K3 fused: h' = rmsnorm(h+agg)*cnw; y = relu(h' @ Wh^T);
//           out = rmsnorm(h'+y)*hnw;  [if do_conv] m = relu(out @ Wc^T)
// =====================================================================
__global__ void __launch_bounds__(128, 4) k_fused(
    const float* __restrict__ h, const float* __restrict__ agg,
    const float* __restrict__ Wh, const float* __restrict__ cnw,
    const float* __restrict__ hnw, float* __restrict__ out,
    const float* __restrict__ Wc, int do_conv, float* __restrict__ m)
{
    extern __shared__ char smem[];
    float* cn = (float*)(smem + OF_CN);
    float* hn = (float*)(smem + OF_HN);
    int tid = threadIdx.x;

    if (tid < HID) {
        cn[tid] = __ldg(cnw + tid);
        hn[tid] = __ldg(hnw + tid);
    }
    load_W_split(smem, Wh, tid);

    int node = blockIdx.x * 128 + tid;
    bool valid = node < N_NODES;
    {
        const float4* hr = (const float4*)(h   + (size_t)node * HID);
        const float4* ar = (const float4*)(agg + (size_t)node * HID);
        float v[64];
        float sq = 0.f;
#pragma unroll
        for (int c = 0; c < 16; c++) {
            float4 a = valid ? __ldg(hr + c) : make_float4(0.f, 0.f, 0.f, 0.f);
            float4 b = valid ? __ldg(ar + c) : make_float4(0.f, 0.f, 0.f, 0.f);
            float z0 = a.x + b.x, z1 = a.y + b.y, z2 = a.z + b.z, z3 = a.w + b.w;
            v[4*c] = z0; v[4*c+1] = z1; v[4*c+2] = z2; v[4*c+3] = z3;
            sq = fmaf(z0, z0, sq); sq = fmaf(z1, z1, sq);
            sq = fmaf(z2, z2, sq); sq = fmaf(z3, z3, sq);
        }
        __syncthreads();          // cn ready (also covers W writes vs below reads)
        float inv1 = rsqrtf(sq * (1.f / HID) + EPS);
#pragma unroll
        for (int k = 0; k < 64; k++) v[k] = v[k] * inv1 * cn[k];
        store_A_split(smem, tid, v);
    }
    __syncthreads();

    int wid = tid >> 5, lane = tid & 31, g = lane >> 2, q = lane & 3;
    uint32_t* Ah = (uint32_t*)(smem + OF_AHI);
    uint32_t* Al = (uint32_t*)(smem + OF_ALO);

    // ---- hidden GEMM + norm2 epilogue (writes out + re-splits into A) ----
#pragma unroll
    for (int mt = 0; mt < 2; mt++) {
        int rbase = 32 * wid + 16 * mt;
        float acc[8][4], acc2[8][4];
        mma_mtile(smem, rbase, g, q, acc, acc2);

#pragma unroll
        for (int half = 0; half < 2; half++) {
            int r = rbase + g + 8 * half;
            int nd = blockIdx.x * 128 + r;
            int sw = (r & 7) << 2;
            float2 z[8];
            float sq2 = 0.f;
#pragma unroll
            for (int nt = 0; nt < 8; nt++) {
                int idx = r * 32 + ((4 * nt + q) ^ sw);
                float2 hv = h2f2(Ah[idx]);
                float2 lv = h2f2(Al[idx]);
                float h0 = hv.x + lv.x * LO_INV;
                float h1 = hv.y + lv.y * LO_INV;
                float y0 = acc[nt][2*half]     + acc2[nt][2*half]     * LO_INV;
                float y1 = acc[nt][2*half + 1] + acc2[nt][2*half + 1] * LO_INV;
                float z0 = h0 + fmaxf(y0, 0.f);
                float z1 = h1 + fmaxf(y1, 0.f);
                z[nt] = make_float2(z0, z1);
                sq2 = fmaf(z0, z0, sq2);
                sq2 = fmaf(z1, z1, sq2);
            }
            sq2 += __shfl_xor_sync(0xffffffffu, sq2, 1);
            sq2 += __shfl_xor_sync(0xffffffffu, sq2, 2);
            float inv2 = rsqrtf(sq2 * (1.f / HID) + EPS);

            float* orow = out + (size_t)nd * HID + 2 * q;
#pragma unroll
            for (int nt = 0; nt < 8; nt++) {
                float z0 = z[nt].x * inv2 * hn[8 * nt + 2 * q];
                float z1 = z[nt].y * inv2 * hn[8 * nt + 2 * q + 1];
                if (nd < N_NODES)
                    *(float2*)(orow + 8 * nt) = make_float2(z0, z1);
                // re-split into A tile for the fused conv GEMM
                int idx = r * 32 + ((4 * nt + q) ^ sw);
                uint32_t hb = pack_h2(z0, z1);
                float2 hf = h2f2(hb);
                Ah[idx] = hb;
                Al[idx] = pack_h2((z0 - hf.x) * LO_SCALE, (z1 - hf.y) * LO_SCALE);
            }
        }
    }

    if (!do_conv) return;

    // ---- swap W buffer to next layer's conv weights ----
    __syncthreads();
    load_W_split(smem, Wc, tid);
    __syncthreads();

    // ---- conv GEMM on the normalized output rows ----
#pragma unroll
    for (int mt = 0; mt < 2; mt++) {
        int rbase = 32 * wid + 16 * mt;
        float acc[8][4], acc2[8][4];
        mma_mtile(smem, rbase, g, q, acc, acc2);

        int n0 = blockIdx.x * 128 + rbase + g;
        int n1 = n0 + 8;
        if (n0 < N_NODES) {
            float* mr = m + (size_t)n0 * HID + 2 * q;
#pragma unroll
            for (int nt = 0; nt < 8; nt++) {
                float y0 = acc[nt][0] + acc2[nt][0] * LO_INV;
                float y1 = acc[nt][1] + acc2[nt][1] * LO_INV;
                *(float2*)(mr + 8 * nt) = make_float2(fmaxf(y0, 0.f), fmaxf(y1, 0.f));
            }
        }
        if (n1 < N_NODES) {
            float* mr = m + (size_t)n1 * HID + 2 * q;
#pragma unroll
            for (int nt = 0; nt < 8; nt++) {
                float y0 = acc[nt][2] + acc2[nt][2] * LO_INV;
                float y1 = acc[nt][3] + acc2[nt][3] * LO_INV;
                *(float2*)(mr + 8 * nt) = make_float2(fmaxf(y0, 0.f), fmaxf(y1, 0.f));
            }
        }
    }
}

// =====================================================================
extern "C" void kernel_launch(void* const* d_in, const int* in_sizes, int n_in,
                              void* d_out, int out_size)
{
    const float* x         = (const float*)d_in[0];
    const float* conv_w    = (const float*)d_in[1];
    const float* conv_norm = (const float*)d_in[2];
    const float* hid_w     = (const float*)d_in[3];
    const float* hid_norm  = (const float*)d_in[4];
    const int*   row       = (const int*)d_in[5];
    const int*   col       = (const int*)d_in[6];
    float*       out       = (float*)d_out;

    float *mp = nullptr, *ap = nullptr, *hp = nullptr;
    int   *dp = nullptr;
    cudaGetSymbolAddress((void**)&mp, g_m);
    cudaGetSymbolAddress((void**)&ap, g_agg);
    cudaGetSymbolAddress((void**)&hp, g_h);
    cudaGetSymbolAddress((void**)&dp, g_deg);

    cudaFuncSetAttribute(k_conv0, cudaFuncAttributeMaxDynamicSharedMemorySize, SMEM_BYTES);
    cudaFuncSetAttribute(k_fused, cudaFuncAttributeMaxDynamicSharedMemorySize, SMEM_BYTES);

    cudaMemsetAsync(dp, 0, N_NODES * sizeof(int));
    k_build<<<(N_EDGES + 255) / 256, 256>>>(row, col);

    const int NB = (N_NODES + 127) / 128;
    const int AB = (N_NODES + 15) / 16;

    k_conv0<<<NB, 128, SMEM_BYTES>>>(x, conv_w, mp);
    for (int l = 0; l < N_LAYERS; l++) {
        const float* hsrc = (l == 0) ? x : hp;
        float* hdst = (l == N_LAYERS - 1) ? out : hp;
        int do_conv = (l < N_LAYERS - 1) ? 1 : 0;
        const float* wc_next = conv_w + (do_conv ? (l + 1) * HID * HID : 0);
        k_agg<<<AB, 256>>>((const float4*)mp, (float4*)ap);
        k_fused<<<NB, 128, SMEM_BYTES>>>(hsrc, ap, hid_w + l * HID * HID,
                                         conv_norm + l * HID, hid_norm + l * HID,
                                         hdst, wc_next, do_conv, mp);
    }
}